// round 12
// baseline (speedup 1.0000x reference)
#include <cuda_runtime.h>
#include <cuda_bf16.h>

// NMU forward: y[b,o] = prod_d ( M_hat[d,o]*x[b,d] + (1 - M_hat[d,o]) )
//            = prod_d ( M_hat[d,o]*(x[b,d]-1) + 1 )
// B=16384, D=256, O=32, fp32.
//
// R12 = R8 (best: 15.49us) with auxiliary fma-pipe work trimmed.
// Model: f32x2 fma/mul occupy the FMA pipe ~4 cyc/SMSP -> the 2-fp32-ops-per-
// term core (1 fma + 1 mul) is the roofline (~28.3K cyc). This round removes
// the per-row scalar lohi FMUL (packed STS.64 partials) and halves epilogue
// math (packed mul tree), keeping the proven hot loop identical.
//  - block = 256 thr (8 warps), warp owns 32 d's, lane = o, 16 rows/block.
//  - m2[16] packed (m[d],m[d+1]) in regs; u = x-1 staged d-major in smem.
//  - hot loop/row: 8 bcast LDS.128 + 16 fma2 + 15 mul2 (4 chains) -> STS.64.
//  - epilogue: 2 cells/thread, 8 packed slab loads + 7 f2_mul + 1 FMUL.

#define NMU_D   256
#define NMU_O   32
#define NMU_R   16        // rows per block
#define NMU_NW  8         // warps per block
#define NMU_DPW 32        // d's per warp

#define NMU_ONE2 0x3f8000003f800000ULL

__device__ __forceinline__ unsigned long long f2_fma(unsigned long long a,
                                                     unsigned long long b,
                                                     unsigned long long c) {
    unsigned long long d;
    asm("fma.rn.f32x2 %0, %1, %2, %3;" : "=l"(d) : "l"(a), "l"(b), "l"(c));
    return d;
}
__device__ __forceinline__ unsigned long long f2_mul(unsigned long long a,
                                                     unsigned long long b) {
    unsigned long long d;
    asm("mul.rn.f32x2 %0, %1, %2;" : "=l"(d) : "l"(a), "l"(b));
    return d;
}
__device__ __forceinline__ unsigned long long pack2(float a, float b) {
    unsigned long long d;
    asm("mov.b64 %0, {%1, %2};" : "=l"(d)
        : "r"(__float_as_uint(a)), "r"(__float_as_uint(b)));
    return d;
}

extern __shared__ float nmu_sm[];

__global__ void __launch_bounds__(256, 4)
nmu_kernel(const float* __restrict__ x, const float* __restrict__ M,
           float* __restrict__ out) {
    float* xs = nmu_sm;                                        // 16 KB (x-1)
    unsigned long long* pw =
        (unsigned long long*)(nmu_sm + NMU_R * NMU_D);         // 32 KB packed

    const int tid  = threadIdx.x;
    const int warp = tid >> 5;
    const int o    = tid & 31;
    const int b0   = blockIdx.x * NMU_R;
    const int d0   = warp * NMU_DPW;

    // --- weights: 16 packed m-pairs in registers (coalesced, L1/L2-hot) ---
    unsigned long long m2[16];
    {
        const float* __restrict__ Mg = M + (size_t)d0 * NMU_O + o;
        #pragma unroll
        for (int k = 0; k < 16; k++) {
            float a = __saturatef(__ldg(Mg + (2 * k + 0) * NMU_O));
            float b = __saturatef(__ldg(Mg + (2 * k + 1) * NMU_O));
            m2[k] = pack2(a, b);
        }
    }

    // --- stage u = x - 1 (coalesced float4, subtract folded into copy) ---
    {
        const float4* __restrict__ xg = (const float4*)(x + (size_t)b0 * NMU_D);
        float4* xs4 = (float4*)xs;
        #pragma unroll
        for (int i = 0; i < (NMU_R * NMU_D / 4) / 256; i++) {   // 4 iters
            float4 v = __ldg(xg + tid + i * 256);
            v.x -= 1.0f; v.y -= 1.0f; v.z -= 1.0f; v.w -= 1.0f;
            xs4[tid + i * 256] = v;
        }
    }
    __syncthreads();

    // --- hot loop: 16 rows; 4 independent product chains per row ---
    #pragma unroll 2
    for (int r = 0; r < NMU_R; r++) {
        const ulonglong2* __restrict__ ur =
            (const ulonglong2*)(xs + r * NMU_D + d0);

        unsigned long long c0, c1, c2, c3;
        {
            ulonglong2 v0 = ur[0], v1 = ur[1];
            c0 = f2_fma(m2[0], v0.x, NMU_ONE2);
            c1 = f2_fma(m2[1], v0.y, NMU_ONE2);
            c2 = f2_fma(m2[2], v1.x, NMU_ONE2);
            c3 = f2_fma(m2[3], v1.y, NMU_ONE2);
        }
        {
            ulonglong2 v2 = ur[2], v3 = ur[3];
            c0 = f2_mul(c0, f2_fma(m2[4], v2.x, NMU_ONE2));
            c1 = f2_mul(c1, f2_fma(m2[5], v2.y, NMU_ONE2));
            c2 = f2_mul(c2, f2_fma(m2[6], v3.x, NMU_ONE2));
            c3 = f2_mul(c3, f2_fma(m2[7], v3.y, NMU_ONE2));
        }
        {
            ulonglong2 v4 = ur[4], v5 = ur[5];
            c0 = f2_mul(c0, f2_fma(m2[ 8], v4.x, NMU_ONE2));
            c1 = f2_mul(c1, f2_fma(m2[ 9], v4.y, NMU_ONE2));
            c2 = f2_mul(c2, f2_fma(m2[10], v5.x, NMU_ONE2));
            c3 = f2_mul(c3, f2_fma(m2[11], v5.y, NMU_ONE2));
        }
        {
            ulonglong2 v6 = ur[6], v7 = ur[7];
            c0 = f2_mul(c0, f2_fma(m2[12], v6.x, NMU_ONE2));
            c1 = f2_mul(c1, f2_fma(m2[13], v6.y, NMU_ONE2));
            c2 = f2_mul(c2, f2_fma(m2[14], v7.x, NMU_ONE2));
            c3 = f2_mul(c3, f2_fma(m2[15], v7.y, NMU_ONE2));
        }
        // packed partial (no lohi mul here): STS.64, 2-phase conflict-free
        pw[(warp * NMU_R + r) * NMU_O + o] =
            f2_mul(f2_mul(c0, c1), f2_mul(c2, c3));
    }
    __syncthreads();

    // --- epilogue: 2 cells/thread; packed mul tree over 8 warp slabs ---
    #pragma unroll
    for (int i = 0; i < 2; i++) {
        const int idx = tid + i * 256;       // 0..511
        const int row = idx >> 5;            // 0..15
        const int oo  = idx & 31;
        const unsigned long long* __restrict__ pp =
            pw + row * NMU_O + oo;
        const int S = NMU_R * NMU_O;         // 512 ull between warp slabs
        unsigned long long a0 = f2_mul(pp[0 * S], pp[1 * S]);
        unsigned long long a1 = f2_mul(pp[2 * S], pp[3 * S]);
        unsigned long long a2 = f2_mul(pp[4 * S], pp[5 * S]);
        unsigned long long a3 = f2_mul(pp[6 * S], pp[7 * S]);
        unsigned long long pr = f2_mul(f2_mul(a0, a1), f2_mul(a2, a3));
        float lo = __uint_as_float((unsigned)(pr & 0xffffffffULL));
        float hi = __uint_as_float((unsigned)(pr >> 32));
        out[(size_t)(b0 + row) * NMU_O + oo] = lo * hi;
    }
}

extern "C" void kernel_launch(void* const* d_in, const int* in_sizes, int n_in,
                              void* d_out, int out_size) {
    const float* x = (const float*)d_in[0];   // [16384, 256]
    const float* M = (const float*)d_in[1];   // [256, 32]
    float* out = (float*)d_out;               // [16384, 32]

    const int B = in_sizes[0] / NMU_D;        // 16384

    const size_t smem_bytes = (size_t)NMU_R * NMU_D * sizeof(float)        // 16 KB
                            + (size_t)NMU_NW * NMU_R * NMU_O * 8;          // 32 KB
    cudaFuncSetAttribute(nmu_kernel,
                         cudaFuncAttributeMaxDynamicSharedMemorySize,
                         (int)smem_bytes);

    nmu_kernel<<<B / NMU_R, 256, smem_bytes>>>(x, M, out);
}

// round 13
// speedup vs baseline: 1.0152x; 1.0152x over previous
#include <cuda_runtime.h>
#include <cuda_bf16.h>

// NMU forward: y[b,o] = prod_d ( M_hat[d,o]*x[b,d] + (1 - M_hat[d,o]) )
// B=16384, D=256, O=32, fp32.
//
// R13 = R8 skeleton + divide-through-by-m transform to kill 3-operand FMAs.
//   t = m*x + (1-m) = m_eff*(x + w),  w = (1-m)/m_eff,  m_eff = max(m,1e-15)
//   prod_d t = (prod m_eff) * prod (x_d + w_d)
// Hot loop per row: 16 add2 (rt2, 2-operand) + 16 mul2 (rt2) instead of
// 16 fma2 (rt3, 3-operand) + 16 mul2 -> ~17% fewer RF-bank-bound cycles.
//   - block = 256 thr (8 warps), warp owns 32 d's, lane = o, 16 rows/block.
//   - w2[16] packed (w[d],w[d+1]) + PmAll2 packed prefactor in regs.
//   - x staged RAW in smem (no x-1 transform needed).
//   - scalar pw partials + R8 epilogue (R12 showed packed-pw variant is slower).

#define NMU_D   256
#define NMU_O   32
#define NMU_R   16        // rows per block
#define NMU_NW  8         // warps per block
#define NMU_DPW 32        // d's per warp

__device__ __forceinline__ unsigned long long f2_add(unsigned long long a,
                                                     unsigned long long b) {
    unsigned long long d;
    asm("add.rn.f32x2 %0, %1, %2;" : "=l"(d) : "l"(a), "l"(b));
    return d;
}
__device__ __forceinline__ unsigned long long f2_mul(unsigned long long a,
                                                     unsigned long long b) {
    unsigned long long d;
    asm("mul.rn.f32x2 %0, %1, %2;" : "=l"(d) : "l"(a), "l"(b));
    return d;
}
__device__ __forceinline__ unsigned long long pack2(float a, float b) {
    unsigned long long d;
    asm("mov.b64 %0, {%1, %2};" : "=l"(d)
        : "r"(__float_as_uint(a)), "r"(__float_as_uint(b)));
    return d;
}
__device__ __forceinline__ float f2_lohi_mul(unsigned long long v) {
    float lo = __uint_as_float((unsigned)(v & 0xffffffffULL));
    float hi = __uint_as_float((unsigned)(v >> 32));
    return lo * hi;
}

__global__ void __launch_bounds__(256, 4)
nmu_kernel(const float* __restrict__ x, const float* __restrict__ M,
           float* __restrict__ out) {
    __shared__ float xs[NMU_R * NMU_D];            // 16 KB  (raw x)
    __shared__ float pw[NMU_NW * NMU_R * NMU_O];   // 16 KB  partials

    const int tid  = threadIdx.x;
    const int warp = tid >> 5;
    const int o    = tid & 31;
    const int b0   = blockIdx.x * NMU_R;
    const int d0   = warp * NMU_DPW;

    // --- weight transform: w2[16] = packed (1-m)/m_eff, PmAll2 = prod m_eff ---
    unsigned long long w2[16];
    unsigned long long PmAll2;
    {
        const float* __restrict__ Mg = M + (size_t)d0 * NMU_O + o;
        float pm_lo = 1.0f, pm_hi = 1.0f;
        #pragma unroll
        for (int k = 0; k < 16; k++) {
            float a = __saturatef(__ldg(Mg + (2 * k + 0) * NMU_O));
            float b = __saturatef(__ldg(Mg + (2 * k + 1) * NMU_O));
            float ae = fmaxf(a, 1e-15f);
            float be = fmaxf(b, 1e-15f);
            float wa = __fdividef(1.0f - a, ae);
            float wb = __fdividef(1.0f - b, be);
            w2[k] = pack2(wa, wb);
            pm_lo *= ae;
            pm_hi *= be;
        }
        PmAll2 = pack2(pm_lo, pm_hi);
    }

    // --- stage raw x (coalesced float4; no transform) ---
    {
        const float4* __restrict__ xg = (const float4*)(x + (size_t)b0 * NMU_D);
        float4* xs4 = (float4*)xs;
        #pragma unroll
        for (int i = 0; i < (NMU_R * NMU_D / 4) / 256; i++)     // 4 iters
            xs4[tid + i * 256] = __ldg(xg + tid + i * 256);
    }
    __syncthreads();

    // --- hot loop: 16 rows; 16 independent add2 + mul2 tree per row ---
    #pragma unroll 2
    for (int r = 0; r < NMU_R; r++) {
        const ulonglong2* __restrict__ ur =
            (const ulonglong2*)(xs + r * NMU_D + d0);

        unsigned long long s0, s1, s2, s3, t01, t23;
        unsigned long long q0, q1, q2, q3;
        {
            ulonglong2 v0 = ur[0], v1 = ur[1];
            s0 = f2_add(v0.x, w2[0]);
            s1 = f2_add(v0.y, w2[1]);
            s2 = f2_add(v1.x, w2[2]);
            s3 = f2_add(v1.y, w2[3]);
            t01 = f2_mul(s0, s1);  t23 = f2_mul(s2, s3);
            q0 = f2_mul(t01, t23);
        }
        {
            ulonglong2 v2 = ur[2], v3 = ur[3];
            s0 = f2_add(v2.x, w2[4]);
            s1 = f2_add(v2.y, w2[5]);
            s2 = f2_add(v3.x, w2[6]);
            s3 = f2_add(v3.y, w2[7]);
            t01 = f2_mul(s0, s1);  t23 = f2_mul(s2, s3);
            q1 = f2_mul(t01, t23);
        }
        {
            ulonglong2 v4 = ur[4], v5 = ur[5];
            s0 = f2_add(v4.x, w2[ 8]);
            s1 = f2_add(v4.y, w2[ 9]);
            s2 = f2_add(v5.x, w2[10]);
            s3 = f2_add(v5.y, w2[11]);
            t01 = f2_mul(s0, s1);  t23 = f2_mul(s2, s3);
            q2 = f2_mul(t01, t23);
        }
        {
            ulonglong2 v6 = ur[6], v7 = ur[7];
            s0 = f2_add(v6.x, w2[12]);
            s1 = f2_add(v6.y, w2[13]);
            s2 = f2_add(v7.x, w2[14]);
            s3 = f2_add(v7.y, w2[15]);
            t01 = f2_mul(s0, s1);  t23 = f2_mul(s2, s3);
            q3 = f2_mul(t01, t23);
        }

        // pr = PmAll * prod(x+w); packed until the final scalar combine
        unsigned long long pr =
            f2_mul(f2_mul(f2_mul(q0, q1), f2_mul(q2, q3)), PmAll2);
        pw[(warp * NMU_R + r) * NMU_O + o] = f2_lohi_mul(pr);   // STS.32
    }
    __syncthreads();

    // --- combine 8 warp-partials; 2 outputs per thread (R8 epilogue) ---
    #pragma unroll
    for (int i = 0; i < 2; i++) {
        const int idx = tid + i * 256;      // 0..511
        const int row = idx >> 5;           // 0..15
        const int oo  = idx & 31;
        const float* pp = pw + row * NMU_O + oo;
        const int S = NMU_R * NMU_O;        // 512 floats between warp slabs
        float a0 = pp[0 * S] * pp[1 * S];
        float a1 = pp[2 * S] * pp[3 * S];
        float a2 = pp[4 * S] * pp[5 * S];
        float a3 = pp[6 * S] * pp[7 * S];
        out[(size_t)(b0 + row) * NMU_O + oo] = (a0 * a1) * (a2 * a3);
    }
}

extern "C" void kernel_launch(void* const* d_in, const int* in_sizes, int n_in,
                              void* d_out, int out_size) {
    const float* x = (const float*)d_in[0];   // [16384, 256]
    const float* M = (const float*)d_in[1];   // [256, 32]
    float* out = (float*)d_out;               // [16384, 32]

    const int B = in_sizes[0] / NMU_D;        // 16384

    nmu_kernel<<<B / NMU_R, 256>>>(x, M, out);
}